// round 15
// baseline (speedup 1.0000x reference)
#include <cuda_runtime.h>
#include <math.h>
#include <string.h>

#define BATCH  64
#define TSTEPS 512
#define DIN    512
#define DH     1024
#define NWORK  20     // worker blocks (128 + 20 = 148 <= SM count)

typedef unsigned long long ull;

// ---------------- small helpers ----------------
__device__ __forceinline__ ull f2u(float2 v) { ull r; memcpy(&r, &v, 8); return r; }
__device__ __forceinline__ float2 u2f(ull v) { float2 r; memcpy(&r, &v, 8); return r; }
__device__ __forceinline__ ull pack2(float v) {
    ull r; asm("mov.b64 %0, {%1, %1};" : "=l"(r) : "f"(v)); return r;
}
__device__ __forceinline__ void fma2(ull& acc, ull a, ull b) {
    asm("fma.rn.f32x2 %0, %1, %2, %0;" : "+l"(acc) : "l"(a), "l"(b));
}
__device__ __forceinline__ ull ld_acq(const ull* p) {
    ull v;
    asm volatile("ld.acquire.gpu.global.u64 %0, [%1];" : "=l"(v) : "l"(p) : "memory");
    return v;
}
__device__ __forceinline__ void red_rel_add(ull* p, ull v) {
    asm volatile("red.release.gpu.global.add.u64 [%0], %1;" :: "l"(p), "l"(v) : "memory");
}
__device__ __forceinline__ unsigned s2u(const void* p) {
    unsigned a;
    asm("{ .reg .u64 t; cvta.to.shared.u64 t, %1; cvt.u32.u64 %0, t; }" : "=r"(a) : "l"(p));
    return a;
}
__device__ __forceinline__ void cp_async16(unsigned dst, const void* src) {
    asm volatile("cp.async.cg.shared.global [%0], [%1], 16;" :: "r"(dst), "l"(src) : "memory");
}
__device__ __forceinline__ void cp_commit() {
    asm volatile("cp.async.commit_group;" ::: "memory");
}
template <int N>
__device__ __forceinline__ void cp_wait() {
    asm volatile("cp.async.wait_group %0;" :: "n"(N) : "memory");
}

// ---------------- global flags ----------------
__device__ ull g_flags[2][16];     // recurrence dataflow (monotonic, replay-safe)
__device__ ull g_pflags[2][4];     // preact readiness per (gm, tq); reset by prefix

// ---------------- Prefix GEMM: tq in {0,1} tiles (r10 gemm, remapped) ------
__global__ __launch_bounds__(256) void gemm_prefix(
    const float* __restrict__ X, const float* __restrict__ W,
    const float* __restrict__ bias, float* __restrict__ C)
{
    // reset worker flags (racy identical-value writes; fused launch is ordered after)
    if (threadIdx.x < 8) ((ull*)g_pflags)[threadIdx.x] = 0ull;

    __shared__ float As[16][132];
    __shared__ float Bs[16][132];

    const int tid   = threadIdx.x;
    const int tx    = tid & 15;
    const int ty    = tid >> 4;
    const int b     = (int)(blockIdx.y >> 1);
    const int tq    = (int)(blockIdx.y & 1);
    const int mBase = ((b << 2) | tq) << 7;     // tile rows = batch b, times [tq*128,+128)
    const int nBase = (int)(blockIdx.x << 7);

    ull acc[4][8];
#pragma unroll
    for (int p = 0; p < 4; ++p)
#pragma unroll
        for (int n = 0; n < 8; ++n) acc[p][n] = 0ull;

    for (int k0 = 0; k0 < DIN; k0 += 16) {
#pragma unroll
        for (int p = 0; p < 2; ++p) {
            int idx = tid + p * 256;
            int m = idx >> 2, kq = (idx & 3) << 2;
            float4 v = *(const float4*)(X + (size_t)(mBase + m) * DIN + k0 + kq);
            As[kq + 0][m] = v.x;
            As[kq + 1][m] = v.y;
            As[kq + 2][m] = v.z;
            As[kq + 3][m] = v.w;
        }
#pragma unroll
        for (int p = 0; p < 2; ++p) {
            int idx = tid + p * 256;
            int k = idx >> 5, nq = (idx & 31) << 2;
            *(float4*)&Bs[k][nq] = *(const float4*)(W + (size_t)(k0 + k) * DH + nBase + nq);
        }
        __syncthreads();
#pragma unroll
        for (int kk = 0; kk < 16; ++kk) {
            float4 a0 = *(const float4*)&As[kk][ty * 8];
            float4 a1 = *(const float4*)&As[kk][ty * 8 + 4];
            float4 b0 = *(const float4*)&Bs[kk][tx * 8];
            float4 b1 = *(const float4*)&Bs[kk][tx * 8 + 4];
            ull am[4];
            am[0] = f2u(make_float2(a0.x, a0.y));
            am[1] = f2u(make_float2(a0.z, a0.w));
            am[2] = f2u(make_float2(a1.x, a1.y));
            am[3] = f2u(make_float2(a1.z, a1.w));
            ull bn[8];
            bn[0] = pack2(b0.x); bn[1] = pack2(b0.y); bn[2] = pack2(b0.z); bn[3] = pack2(b0.w);
            bn[4] = pack2(b1.x); bn[5] = pack2(b1.y); bn[6] = pack2(b1.z); bn[7] = pack2(b1.w);
#pragma unroll
            for (int p = 0; p < 4; ++p)
#pragma unroll
                for (int n = 0; n < 8; ++n)
                    fma2(acc[p][n], am[p], bn[n]);
        }
        __syncthreads();
    }

    float4 bb0 = *(const float4*)(bias + nBase + tx * 8);
    float4 bb1 = *(const float4*)(bias + nBase + tx * 8 + 4);
    float bbs[8] = {bb0.x, bb0.y, bb0.z, bb0.w, bb1.x, bb1.y, bb1.z, bb1.w};

#pragma unroll
    for (int p = 0; p < 4; ++p) {
        float2 c[8];
#pragma unroll
        for (int n = 0; n < 8; ++n) c[n] = u2f(acc[p][n]);
        int row0 = mBase + ty * 8 + p * 2;
        float* out0 = C + (size_t)row0 * DH + nBase + tx * 8;
        float* out1 = out0 + DH;
        float4 o;
        o.x = c[0].x + bbs[0]; o.y = c[1].x + bbs[1]; o.z = c[2].x + bbs[2]; o.w = c[3].x + bbs[3];
        *(float4*)out0 = o;
        o.x = c[4].x + bbs[4]; o.y = c[5].x + bbs[5]; o.z = c[6].x + bbs[6]; o.w = c[7].x + bbs[7];
        *(float4*)(out0 + 4) = o;
        o.x = c[0].y + bbs[0]; o.y = c[1].y + bbs[1]; o.z = c[2].y + bbs[2]; o.w = c[3].y + bbs[3];
        *(float4*)out1 = o;
        o.x = c[4].y + bbs[4]; o.y = c[5].y + bbs[5]; o.z = c[6].y + bbs[6]; o.w = c[7].y + bbs[7];
        *(float4*)(out1 + 4) = o;
    }
}

// ---------------- Fused kernel: 128 recurrence blocks + NWORK GEMM workers -
#define TPB 512
#define HSTRIDE 1028
#define H_OFF 0
#define R_OFF (32 * HSTRIDE)                  // 32896
#define P_OFF (R_OFF + 16 * HSTRIDE)          // 49344
#define SMEM_FLOATS (P_OFF + 16 * 512)        // 57536 floats = 230144 B

// Worker: 128x128x512 tile with 512 threads (4m x 8n micro, f32x2).
__device__ void worker_gemm(float* S, const float* __restrict__ X,
                            const float* __restrict__ W,
                            const float* __restrict__ bias, float* __restrict__ C,
                            int wid0)
{
    const int tid = threadIdx.x;
    const int tx  = tid & 15;
    const int ty  = tid >> 4;            // 0..31
    float* As = S;                       // [16][132]
    float* Bs = S + 16 * 132;            // [16][132]

#pragma unroll 1
    for (int e = wid0; e < 1024; e += NWORK) {
        const int tq  = 2 + (e >> 9);
        const int rem = e & 511;
        const int b   = rem >> 3;
        const int nx  = rem & 7;
        const int mBase = ((b << 2) | tq) << 7;
        const int nBase = nx << 7;

        ull acc[2][8];
#pragma unroll
        for (int p = 0; p < 2; ++p)
#pragma unroll
            for (int n = 0; n < 8; ++n) acc[p][n] = 0ull;

#pragma unroll 1
        for (int k0 = 0; k0 < DIN; k0 += 16) {
            // stage A transposed [k][m]: thread -> m = tid>>2, kq = (tid&3)*4
            {
                int m = tid >> 2, kq = (tid & 3) << 2;
                float4 v = *(const float4*)(X + (size_t)(mBase + m) * DIN + k0 + kq);
                As[(kq + 0) * 132 + m] = v.x;
                As[(kq + 1) * 132 + m] = v.y;
                As[(kq + 2) * 132 + m] = v.z;
                As[(kq + 3) * 132 + m] = v.w;
            }
            // stage B [k][n]: k = tid>>5, nq = (tid&31)*4
            {
                int k = tid >> 5, nq = (tid & 31) << 2;
                *(float4*)&Bs[k * 132 + nq] =
                    *(const float4*)(W + (size_t)(k0 + k) * DH + nBase + nq);
            }
            __syncthreads();
#pragma unroll
            for (int kk = 0; kk < 16; ++kk) {
                float4 a  = *(const float4*)&As[kk * 132 + ty * 4];
                float4 b0 = *(const float4*)&Bs[kk * 132 + tx * 8];
                float4 b1 = *(const float4*)&Bs[kk * 132 + tx * 8 + 4];
                ull am[2];
                am[0] = f2u(make_float2(a.x, a.y));
                am[1] = f2u(make_float2(a.z, a.w));
                ull bn[8];
                bn[0] = pack2(b0.x); bn[1] = pack2(b0.y); bn[2] = pack2(b0.z); bn[3] = pack2(b0.w);
                bn[4] = pack2(b1.x); bn[5] = pack2(b1.y); bn[6] = pack2(b1.z); bn[7] = pack2(b1.w);
#pragma unroll
                for (int p = 0; p < 2; ++p)
#pragma unroll
                    for (int n = 0; n < 8; ++n)
                        fma2(acc[p][n], am[p], bn[n]);
            }
            __syncthreads();
        }

        float4 bb0 = *(const float4*)(bias + nBase + tx * 8);
        float4 bb1 = *(const float4*)(bias + nBase + tx * 8 + 4);
        float bbs[8] = {bb0.x, bb0.y, bb0.z, bb0.w, bb1.x, bb1.y, bb1.z, bb1.w};

#pragma unroll
        for (int p = 0; p < 2; ++p) {
            float2 c[8];
#pragma unroll
            for (int n = 0; n < 8; ++n) c[n] = u2f(acc[p][n]);
            int row0 = mBase + ty * 4 + p * 2;
            float* out0 = C + (size_t)row0 * DH + nBase + tx * 8;
            float* out1 = out0 + DH;
            float4 o;
            o.x = c[0].x + bbs[0]; o.y = c[1].x + bbs[1]; o.z = c[2].x + bbs[2]; o.w = c[3].x + bbs[3];
            *(float4*)out0 = o;
            o.x = c[4].x + bbs[4]; o.y = c[5].x + bbs[5]; o.z = c[6].x + bbs[6]; o.w = c[7].x + bbs[7];
            *(float4*)(out0 + 4) = o;
            o.x = c[0].y + bbs[0]; o.y = c[1].y + bbs[1]; o.z = c[2].y + bbs[2]; o.w = c[3].y + bbs[3];
            *(float4*)out1 = o;
            o.x = c[4].y + bbs[4]; o.y = c[5].y + bbs[5]; o.z = c[6].y + bbs[6]; o.w = c[7].y + bbs[7];
            *(float4*)(out1 + 4) = o;
        }

        __syncthreads();                        // all STGs issued
        if (tid == 0) red_rel_add(&g_pflags[b >> 5][tq], 1ull);
    }
}

__global__ __launch_bounds__(TPB, 1)
void rnn_fused(const float* __restrict__ x,  const float* __restrict__ h0,
               const float* __restrict__ W,  const float* __restrict__ R,
               const float* __restrict__ bias, float* out)
{
    extern __shared__ float S[];

    // ---------------- worker role ----------------
    if (blockIdx.x >= 128) {
        worker_gemm(S, x, W, bias, out, (int)blockIdx.x - 128);
        return;
    }

    // ---------------- recurrence role (r10 verbatim + tq waits) ----------
    const int tid    = threadIdx.x;
    const int w      = tid >> 5;
    const int lane   = tid & 31;
    const int m_lane = lane & 7;
    const int j_lane = lane >> 3;
    const int gm     = (int)(blockIdx.x >> 6);
    const int gn     = (int)(blockIdx.x & 63);
    const int mBase  = gm << 5;
    const int jBase  = gn << 4;

    const ull* myflag = &g_flags[gm][w];
    ull* prodflag     = &g_flags[gm][gn >> 2];

    ull base0 = 0;
    if (lane == 0) base0 = ld_acq(myflag);
    const ull base = __shfl_sync(0xFFFFFFFFu, base0, 0);

    // ---- stage R transposed into smem [j][k] (once) ----
#pragma unroll
    for (int p = 0; p < 8; ++p) {
        int idx = tid + p * TPB;
        int k = idx >> 2, q = idx & 3;
        float4 v = *(const float4*)(R + (size_t)k * DH + jBase + q * 4);
        S[R_OFF + (q * 4 + 0) * HSTRIDE + k] = v.x;
        S[R_OFF + (q * 4 + 1) * HSTRIDE + k] = v.y;
        S[R_OFF + (q * 4 + 2) * HSTRIDE + k] = v.z;
        S[R_OFF + (q * 4 + 3) * HSTRIDE + k] = v.w;
    }
    __syncthreads();

    const float* Hp = S + H_OFF + (size_t)m_lane * HSTRIDE + w * 64;
    const float* Rp = S + R_OFF + (size_t)j_lane * HSTRIDE + w * 64;

    const int sub  = tid >> 5;
    const int mi_r = sub >> 2, ji_r = sub & 3;
    const int m_r  = ((tid & 31) >> 2) + 8 * mi_r;
    const int j_r  = (tid & 3) + 4 * ji_r;

    const int klocal = (lane & 7) * 4;
    const int rbase  = lane >> 3;

#pragma unroll 1
    for (int t = 0; t < TSTEPS; ++t) {
        // ---- wait for preact quarter from workers (t = 256, 384 only) ----
        if ((t & 127) == 0 && t >= 256) {
            const int tq = t >> 7;
            while (ld_acq(&g_pflags[gm][tq]) < 256ull) { }
        }

        // ---- prefetch this block's preact (own tile; L1-bypass) ----
        const size_t oi = ((size_t)(mBase + m_r) * TSTEPS + t) * DH + jBase + j_r;
        const float pre = __ldcg(out + oi);

        // ---- wait for my chunk's 4 producers to finish step t-1 ----
        if (t > 0) {
            const ull target = base + 4ull * (ull)t;
            while (ld_acq(myflag) < target) { }
        }

        // ---- stage h slice via cp.async in 2 k-half groups ----
        const float* hb;
        size_t rstr;
        if (t == 0) { hb = h0 + (size_t)mBase * DH; rstr = DH; }
        else {
            hb = out + (size_t)(t - 1) * DH + (size_t)mBase * ((size_t)TSTEPS * DH);
            rstr = (size_t)TSTEPS * DH;
        }
#pragma unroll
        for (int g = 0; g < 2; ++g) {
            const int kb = w * 64 + g * 32 + klocal;
#pragma unroll
            for (int p = 0; p < 8; ++p) {
                const int row = rbase + 4 * p;
                cp_async16(s2u(&S[H_OFF + row * HSTRIDE + kb]),
                           hb + (size_t)row * rstr + kb);
            }
            cp_commit();
        }

        ull acc[4][4];
#pragma unroll
        for (int mi = 0; mi < 4; ++mi)
#pragma unroll
            for (int ji = 0; ji < 4; ++ji) acc[mi][ji] = 0ull;

        // ---- compute half 0 while half 1 lands ----
        cp_wait<1>(); __syncwarp();
#pragma unroll
        for (int it = 0; it < 8; ++it) {
            const int off = it * 4;
            float4 h[4], r[4];
#pragma unroll
            for (int mi = 0; mi < 4; ++mi)
                h[mi] = *(const float4*)(Hp + (size_t)(mi * 8) * HSTRIDE + off);
#pragma unroll
            for (int ji = 0; ji < 4; ++ji)
                r[ji] = *(const float4*)(Rp + (size_t)(ji * 4) * HSTRIDE + off);
#pragma unroll
            for (int mi = 0; mi < 4; ++mi) {
                ull hlo = f2u(make_float2(h[mi].x, h[mi].y));
                ull hhi = f2u(make_float2(h[mi].z, h[mi].w));
#pragma unroll
                for (int ji = 0; ji < 4; ++ji) {
                    fma2(acc[mi][ji], hlo, f2u(make_float2(r[ji].x, r[ji].y)));
                    fma2(acc[mi][ji], hhi, f2u(make_float2(r[ji].z, r[ji].w)));
                }
            }
        }

        // ---- compute half 1 ----
        cp_wait<0>(); __syncwarp();
#pragma unroll
        for (int it = 8; it < 16; ++it) {
            const int off = it * 4;
            float4 h[4], r[4];
#pragma unroll
            for (int mi = 0; mi < 4; ++mi)
                h[mi] = *(const float4*)(Hp + (size_t)(mi * 8) * HSTRIDE + off);
#pragma unroll
            for (int ji = 0; ji < 4; ++ji)
                r[ji] = *(const float4*)(Rp + (size_t)(ji * 4) * HSTRIDE + off);
#pragma unroll
            for (int mi = 0; mi < 4; ++mi) {
                ull hlo = f2u(make_float2(h[mi].x, h[mi].y));
                ull hhi = f2u(make_float2(h[mi].z, h[mi].w));
#pragma unroll
                for (int ji = 0; ji < 4; ++ji) {
                    fma2(acc[mi][ji], hlo, f2u(make_float2(r[ji].x, r[ji].y)));
                    fma2(acc[mi][ji], hhi, f2u(make_float2(r[ji].z, r[ji].w)));
                }
            }
        }

        // ---- partials: conflict-free writes (32 lanes -> 32 banks) ----
        {
            float* Pw = S + P_OFF + w * 512;
            const int lbase = m_lane * 4 + j_lane;
#pragma unroll
            for (int mi = 0; mi < 4; ++mi)
#pragma unroll
                for (int ji = 0; ji < 4; ++ji) {
                    float2 c = u2f(acc[mi][ji]);
                    Pw[32 * (mi * 4 + ji) + lbase] = c.x + c.y;
                }
        }
        __syncthreads();   // (a) partials visible

        // ---- reduce 16 partials (contiguous reads) + tanh + store h_t ----
        {
            float s0 = 0.f, s1 = 0.f, s2 = 0.f, s3 = 0.f;
#pragma unroll
            for (int q = 0; q < 4; ++q) {
                s0 += S[P_OFF + (q +  0) * 512 + tid];
                s1 += S[P_OFF + (q +  4) * 512 + tid];
                s2 += S[P_OFF + (q +  8) * 512 + tid];
                s3 += S[P_OFF + (q + 12) * 512 + tid];
            }
            out[oi] = tanhf(pre + (s0 + s1) + (s2 + s3));
        }

        __syncthreads();   // (b) STGs + P reads done (WAR + release ordering)

        // ---- announce: this block finished step t ----
        if (tid == 0) red_rel_add(prodflag, 1ull);
    }
}

// ---------------- launch ----------------
extern "C" void kernel_launch(void* const* d_in, const int* in_sizes, int n_in,
                              void* d_out, int out_size)
{
    const float* x  = (const float*)d_in[0];   // [64,512,512]
    const float* h0 = (const float*)d_in[1];   // [64,1024]
    const float* W  = (const float*)d_in[2];   // [512,1024]
    const float* R  = (const float*)d_in[3];   // [1024,1024]
    const float* b  = (const float*)d_in[4];   // [1,1024]
    float* out = (float*)d_out;                // [64,512,1024]

    const int smem_bytes = SMEM_FLOATS * 4;    // 230144 <= 232448
    cudaFuncSetAttribute(rnn_fused,
                         cudaFuncAttributeMaxDynamicSharedMemorySize, smem_bytes);

    // prefix: preact for tq in {0,1} (also resets g_pflags)
    dim3 gP(DH / 128, 128);                    // (8, 128) = 1024 blocks
    gemm_prefix<<<gP, 256>>>(x, W, b, out);

    // fused: 128 recurrence blocks + NWORK GEMM workers (tq 2,3)
    rnn_fused<<<128 + NWORK, TPB, smem_bytes>>>(x, h0, W, R, b, out);
}

// round 16
// speedup vs baseline: 1.4183x; 1.4183x over previous
#include <cuda_runtime.h>
#include <math.h>
#include <string.h>

#define BATCH  64
#define TSTEPS 512
#define DIN    512
#define DH     1024

typedef unsigned long long ull;

// ---------------- small helpers ----------------
__device__ __forceinline__ ull f2u(float2 v) { ull r; memcpy(&r, &v, 8); return r; }
__device__ __forceinline__ float2 u2f(ull v) { float2 r; memcpy(&r, &v, 8); return r; }
__device__ __forceinline__ ull pack2(float v) {
    ull r; asm("mov.b64 %0, {%1, %1};" : "=l"(r) : "f"(v)); return r;
}
__device__ __forceinline__ void fma2(ull& acc, ull a, ull b) {
    asm("fma.rn.f32x2 %0, %1, %2, %0;" : "+l"(acc) : "l"(a), "l"(b));
}
__device__ __forceinline__ ull ld_acq(const ull* p) {
    ull v;
    asm volatile("ld.acquire.gpu.global.u64 %0, [%1];" : "=l"(v) : "l"(p) : "memory");
    return v;
}
__device__ __forceinline__ void red_rel_add(ull* p, ull v) {
    asm volatile("red.release.gpu.global.add.u64 [%0], %1;" :: "l"(p), "l"(v) : "memory");
}
__device__ __forceinline__ unsigned s2u(const void* p) {
    unsigned a;
    asm("{ .reg .u64 t; cvta.to.shared.u64 t, %1; cvt.u32.u64 %0, t; }" : "=r"(a) : "l"(p));
    return a;
}
__device__ __forceinline__ void cp_async16(unsigned dst, const void* src) {
    asm volatile("cp.async.cg.shared.global [%0], [%1], 16;" :: "r"(dst), "l"(src) : "memory");
}
__device__ __forceinline__ void cp_commit() {
    asm volatile("cp.async.commit_group;" ::: "memory");
}
template <int N>
__device__ __forceinline__ void cp_wait() {
    asm volatile("cp.async.wait_group %0;" :: "n"(N) : "memory");
}

// ---------------- dataflow flags (monotonic, replay-safe) ----------------
__device__ ull g_flags[2][16];

// ---------------- Kernel A: C = x @ W + bias (register double-buffered) ----
// 128x128 tile, 256 threads, k-tile 16. LDG for tile kt+1 issued right after
// staging kt -> L2 latency hides under tile-kt compute. Single smem buffer.
__global__ __launch_bounds__(256) void gemm_xw_kernel(
    const float* __restrict__ X, const float* __restrict__ W,
    const float* __restrict__ bias, float* __restrict__ C)
{
    __shared__ float As[16][132];
    __shared__ float Bs[16][132];

    const int tid   = threadIdx.x;
    const int tx    = tid & 15;
    const int ty    = tid >> 4;
    const int mBase = blockIdx.y << 7;
    const int nBase = blockIdx.x << 7;

    // staging decode (as r10): A transpose scatter, B direct
    const int am0 = tid >> 2;             // A: m row (thread) / p*256 variant
    const int ak0 = (tid & 3) << 2;       // A: k quad
    const int bk0 = tid >> 5;             // B: k row
    const int bn0 = (tid & 31) << 2;      // B: n quad

    float4 aPre[2], bPre[2];

#define LOAD_REGS(kt) {                                                      \
        const int k0 = (kt) * 16;                                            \
        _Pragma("unroll")                                                    \
        for (int p = 0; p < 2; ++p) {                                        \
            int idx = tid + p * 256;                                         \
            int m = idx >> 2, kq = (idx & 3) << 2;                           \
            aPre[p] = *(const float4*)(X + (size_t)(mBase + m) * DIN + k0 + kq); \
            int k = idx >> 5, nq = (idx & 31) << 2;                          \
            bPre[p] = *(const float4*)(W + (size_t)(k0 + k) * DH + nBase + nq); \
        }                                                                    \
    }

#define STS_REGS() {                                                         \
        _Pragma("unroll")                                                    \
        for (int p = 0; p < 2; ++p) {                                        \
            int idx = tid + p * 256;                                         \
            int m = idx >> 2, kq = (idx & 3) << 2;                           \
            As[kq + 0][m] = aPre[p].x;                                       \
            As[kq + 1][m] = aPre[p].y;                                       \
            As[kq + 2][m] = aPre[p].z;                                       \
            As[kq + 3][m] = aPre[p].w;                                       \
            int k = idx >> 5, nq = (idx & 31) << 2;                          \
            *(float4*)&Bs[k][nq] = bPre[p];                                  \
        }                                                                    \
    }

    ull acc[4][8];
#pragma unroll
    for (int p = 0; p < 4; ++p)
#pragma unroll
        for (int n = 0; n < 8; ++n) acc[p][n] = 0ull;

    LOAD_REGS(0)

#pragma unroll 1
    for (int kt = 0; kt < DIN / 16; ++kt) {
        __syncthreads();                 // WAR: previous tile's compute done
        STS_REGS()
        __syncthreads();                 // tile kt visible
        if (kt + 1 < DIN / 16) LOAD_REGS(kt + 1)   // overlaps compute below
#pragma unroll
        for (int kk = 0; kk < 16; ++kk) {
            float4 a0 = *(const float4*)&As[kk][ty * 8];
            float4 a1 = *(const float4*)&As[kk][ty * 8 + 4];
            float4 b0 = *(const float4*)&Bs[kk][tx * 8];
            float4 b1 = *(const float4*)&Bs[kk][tx * 8 + 4];
            ull am[4];
            am[0] = f2u(make_float2(a0.x, a0.y));
            am[1] = f2u(make_float2(a0.z, a0.w));
            am[2] = f2u(make_float2(a1.x, a1.y));
            am[3] = f2u(make_float2(a1.z, a1.w));
            ull bn[8];
            bn[0] = pack2(b0.x); bn[1] = pack2(b0.y); bn[2] = pack2(b0.z); bn[3] = pack2(b0.w);
            bn[4] = pack2(b1.x); bn[5] = pack2(b1.y); bn[6] = pack2(b1.z); bn[7] = pack2(b1.w);
#pragma unroll
            for (int p = 0; p < 4; ++p)
#pragma unroll
                for (int n = 0; n < 8; ++n)
                    fma2(acc[p][n], am[p], bn[n]);
        }
    }
#undef LOAD_REGS
#undef STS_REGS

    float4 bb0 = *(const float4*)(bias + nBase + tx * 8);
    float4 bb1 = *(const float4*)(bias + nBase + tx * 8 + 4);
    float bbs[8] = {bb0.x, bb0.y, bb0.z, bb0.w, bb1.x, bb1.y, bb1.z, bb1.w};

#pragma unroll
    for (int p = 0; p < 4; ++p) {
        float2 c[8];
#pragma unroll
        for (int n = 0; n < 8; ++n) c[n] = u2f(acc[p][n]);
        int row0 = mBase + ty * 8 + p * 2;
        float* out0 = C + (size_t)row0 * DH + nBase + tx * 8;
        float* out1 = out0 + DH;
        float4 o;
        o.x = c[0].x + bbs[0]; o.y = c[1].x + bbs[1]; o.z = c[2].x + bbs[2]; o.w = c[3].x + bbs[3];
        *(float4*)out0 = o;
        o.x = c[4].x + bbs[4]; o.y = c[5].x + bbs[5]; o.z = c[6].x + bbs[6]; o.w = c[7].x + bbs[7];
        *(float4*)(out0 + 4) = o;
        o.x = c[0].y + bbs[0]; o.y = c[1].y + bbs[1]; o.z = c[2].y + bbs[2]; o.w = c[3].y + bbs[3];
        *(float4*)out1 = o;
        o.x = c[4].y + bbs[4]; o.y = c[5].y + bbs[5]; o.z = c[6].y + bbs[6]; o.w = c[7].y + bbs[7];
        *(float4*)(out1 + 4) = o;
    }
}

// ---------------- Kernel B: persistent recurrence (r10, best known) --------
#define TPB 512
#define HSTRIDE 1028
#define H_OFF 0
#define R_OFF (32 * HSTRIDE)                  // 32896
#define P_OFF (R_OFF + 16 * HSTRIDE)          // 49344
#define SMEM_FLOATS (P_OFF + 16 * 512)        // 57536 floats = 230144 B

__global__ __launch_bounds__(TPB, 1)
void rnn_recur_kernel(const float* __restrict__ h0, const float* __restrict__ R, float* out)
{
    extern __shared__ float S[];

    const int tid    = threadIdx.x;
    const int w      = tid >> 5;
    const int lane   = tid & 31;
    const int m_lane = lane & 7;
    const int j_lane = lane >> 3;
    const int gm     = (int)(blockIdx.x >> 6);
    const int gn     = (int)(blockIdx.x & 63);
    const int mBase  = gm << 5;
    const int jBase  = gn << 4;

    const ull* myflag = &g_flags[gm][w];
    ull* prodflag     = &g_flags[gm][gn >> 2];

    // snapshot monotonic flag base (all flags equal at kernel entry)
    ull base0 = 0;
    if (lane == 0) base0 = ld_acq(myflag);
    const ull base = __shfl_sync(0xFFFFFFFFu, base0, 0);

    // ---- stage R transposed into smem [j][k] (once) ----
#pragma unroll
    for (int p = 0; p < 8; ++p) {
        int idx = tid + p * TPB;
        int k = idx >> 2, q = idx & 3;
        float4 v = *(const float4*)(R + (size_t)k * DH + jBase + q * 4);
        S[R_OFF + (q * 4 + 0) * HSTRIDE + k] = v.x;
        S[R_OFF + (q * 4 + 1) * HSTRIDE + k] = v.y;
        S[R_OFF + (q * 4 + 2) * HSTRIDE + k] = v.z;
        S[R_OFF + (q * 4 + 3) * HSTRIDE + k] = v.w;
    }
    __syncthreads();

    const float* Hp = S + H_OFF + (size_t)m_lane * HSTRIDE + w * 64;
    const float* Rp = S + R_OFF + (size_t)j_lane * HSTRIDE + w * 64;

    // epilogue decode: tid -> (m, j) matching conflict-free P layout
    const int sub  = tid >> 5;
    const int mi_r = sub >> 2, ji_r = sub & 3;
    const int m_r  = ((tid & 31) >> 2) + 8 * mi_r;
    const int j_r  = (tid & 3) + 4 * ji_r;

    // staging decode: group g covers k in [w*64 + g*32, +32).
    const int klocal = (lane & 7) * 4;
    const int rbase  = lane >> 3;

#pragma unroll 1
    for (int t = 0; t < TSTEPS; ++t) {
        // ---- prefetch this block's preact (own tile; L1-bypass) ----
        const size_t oi = ((size_t)(mBase + m_r) * TSTEPS + t) * DH + jBase + j_r;
        const float pre = __ldcg(out + oi);

        // ---- wait for my chunk's 4 producers to finish step t-1 ----
        if (t > 0) {
            const ull target = base + 4ull * (ull)t;
            while (ld_acq(myflag) < target) { }
        }

        // ---- stage h slice via cp.async in 2 k-half groups ----
        const float* hb;
        size_t rstr;
        if (t == 0) { hb = h0 + (size_t)mBase * DH; rstr = DH; }
        else {
            hb = out + (size_t)(t - 1) * DH + (size_t)mBase * ((size_t)TSTEPS * DH);
            rstr = (size_t)TSTEPS * DH;
        }
#pragma unroll
        for (int g = 0; g < 2; ++g) {
            const int kb = w * 64 + g * 32 + klocal;
#pragma unroll
            for (int p = 0; p < 8; ++p) {
                const int row = rbase + 4 * p;
                cp_async16(s2u(&S[H_OFF + row * HSTRIDE + kb]),
                           hb + (size_t)row * rstr + kb);
            }
            cp_commit();
        }

        ull acc[4][4];
#pragma unroll
        for (int mi = 0; mi < 4; ++mi)
#pragma unroll
            for (int ji = 0; ji < 4; ++ji) acc[mi][ji] = 0ull;

        // ---- compute half 0 while half 1 lands ----
        cp_wait<1>(); __syncwarp();
#pragma unroll
        for (int it = 0; it < 8; ++it) {
            const int off = it * 4;
            float4 h[4], r[4];
#pragma unroll
            for (int mi = 0; mi < 4; ++mi)
                h[mi] = *(const float4*)(Hp + (size_t)(mi * 8) * HSTRIDE + off);
#pragma unroll
            for (int ji = 0; ji < 4; ++ji)
                r[ji] = *(const float4*)(Rp + (size_t)(ji * 4) * HSTRIDE + off);
#pragma unroll
            for (int mi = 0; mi < 4; ++mi) {
                ull hlo = f2u(make_float2(h[mi].x, h[mi].y));
                ull hhi = f2u(make_float2(h[mi].z, h[mi].w));
#pragma unroll
                for (int ji = 0; ji < 4; ++ji) {
                    fma2(acc[mi][ji], hlo, f2u(make_float2(r[ji].x, r[ji].y)));
                    fma2(acc[mi][ji], hhi, f2u(make_float2(r[ji].z, r[ji].w)));
                }
            }
        }

        // ---- compute half 1 ----
        cp_wait<0>(); __syncwarp();
#pragma unroll
        for (int it = 8; it < 16; ++it) {
            const int off = it * 4;
            float4 h[4], r[4];
#pragma unroll
            for (int mi = 0; mi < 4; ++mi)
                h[mi] = *(const float4*)(Hp + (size_t)(mi * 8) * HSTRIDE + off);
#pragma unroll
            for (int ji = 0; ji < 4; ++ji)
                r[ji] = *(const float4*)(Rp + (size_t)(ji * 4) * HSTRIDE + off);
#pragma unroll
            for (int mi = 0; mi < 4; ++mi) {
                ull hlo = f2u(make_float2(h[mi].x, h[mi].y));
                ull hhi = f2u(make_float2(h[mi].z, h[mi].w));
#pragma unroll
                for (int ji = 0; ji < 4; ++ji) {
                    fma2(acc[mi][ji], hlo, f2u(make_float2(r[ji].x, r[ji].y)));
                    fma2(acc[mi][ji], hhi, f2u(make_float2(r[ji].z, r[ji].w)));
                }
            }
        }

        // ---- partials: conflict-free writes (32 lanes -> 32 banks) ----
        {
            float* Pw = S + P_OFF + w * 512;
            const int lbase = m_lane * 4 + j_lane;
#pragma unroll
            for (int mi = 0; mi < 4; ++mi)
#pragma unroll
                for (int ji = 0; ji < 4; ++ji) {
                    float2 c = u2f(acc[mi][ji]);
                    Pw[32 * (mi * 4 + ji) + lbase] = c.x + c.y;
                }
        }
        __syncthreads();   // (a) partials visible

        // ---- reduce 16 partials (contiguous reads) + tanh + store h_t ----
        {
            float s0 = 0.f, s1 = 0.f, s2 = 0.f, s3 = 0.f;
#pragma unroll
            for (int q = 0; q < 4; ++q) {
                s0 += S[P_OFF + (q +  0) * 512 + tid];
                s1 += S[P_OFF + (q +  4) * 512 + tid];
                s2 += S[P_OFF + (q +  8) * 512 + tid];
                s3 += S[P_OFF + (q + 12) * 512 + tid];
            }
            out[oi] = tanhf(pre + (s0 + s1) + (s2 + s3));
        }

        __syncthreads();   // (b) STGs + P reads done (WAR + release ordering)

        // ---- announce: this block finished step t ----
        if (tid == 0) red_rel_add(prodflag, 1ull);
    }
}

// ---------------- launch ----------------
extern "C" void kernel_launch(void* const* d_in, const int* in_sizes, int n_in,
                              void* d_out, int out_size)
{
    const float* x  = (const float*)d_in[0];   // [64,512,512]
    const float* h0 = (const float*)d_in[1];   // [64,1024]
    const float* W  = (const float*)d_in[2];   // [512,1024]
    const float* R  = (const float*)d_in[3];   // [1024,1024]
    const float* b  = (const float*)d_in[4];   // [1,1024]
    float* out = (float*)d_out;                // [64,512,1024]

    const int smem_bytes = SMEM_FLOATS * 4;    // 230144 <= 232448
    cudaFuncSetAttribute(rnn_recur_kernel,
                         cudaFuncAttributeMaxDynamicSharedMemorySize, smem_bytes);

    dim3 gridA(DH / 128, (BATCH * TSTEPS) / 128);  // (8, 256)
    gemm_xw_kernel<<<gridA, 256>>>(x, W, b, out);

    rnn_recur_kernel<<<128, TPB, smem_bytes>>>(h0, R, out);
}

// round 17
// speedup vs baseline: 1.6240x; 1.1450x over previous
#include <cuda_runtime.h>
#include <math.h>
#include <string.h>

#define BATCH  64
#define TSTEPS 512
#define DIN    512
#define DH     1024

typedef unsigned long long ull;

// ---------------- small helpers ----------------
__device__ __forceinline__ ull f2u(float2 v) { ull r; memcpy(&r, &v, 8); return r; }
__device__ __forceinline__ float2 u2f(ull v) { float2 r; memcpy(&r, &v, 8); return r; }
__device__ __forceinline__ ull pack2(float v) {
    ull r; asm("mov.b64 %0, {%1, %1};" : "=l"(r) : "f"(v)); return r;
}
__device__ __forceinline__ void fma2(ull& acc, ull a, ull b) {
    asm("fma.rn.f32x2 %0, %1, %2, %0;" : "+l"(acc) : "l"(a), "l"(b));
}
__device__ __forceinline__ ull ld_acq(const ull* p) {
    ull v;
    asm volatile("ld.acquire.gpu.global.u64 %0, [%1];" : "=l"(v) : "l"(p) : "memory");
    return v;
}
__device__ __forceinline__ void red_rel_add(ull* p, ull v) {
    asm volatile("red.release.gpu.global.add.u64 [%0], %1;" :: "l"(p), "l"(v) : "memory");
}
__device__ __forceinline__ unsigned s2u(const void* p) {
    unsigned a;
    asm("{ .reg .u64 t; cvta.to.shared.u64 t, %1; cvt.u32.u64 %0, t; }" : "=r"(a) : "l"(p));
    return a;
}
__device__ __forceinline__ void cp_async16(unsigned dst, const void* src) {
    asm volatile("cp.async.cg.shared.global [%0], [%1], 16;" :: "r"(dst), "l"(src) : "memory");
}
__device__ __forceinline__ void cp_commit() {
    asm volatile("cp.async.commit_group;" ::: "memory");
}
template <int N>
__device__ __forceinline__ void cp_wait() {
    asm volatile("cp.async.wait_group %0;" :: "n"(N) : "memory");
}

// ---------------- dataflow flags (monotonic, replay-safe) ----------------
// One flag per (gm, 64-col chunk), PADDED: each flag owns a 256-byte slot
// (32 ull). 256B (not 128B) because L2's addr->LTS hash ignores bit 7 --
// 128B-strided lines would pair-collide on the same LTS slice. Removes the
// single-line hotspot where 64 red.release/step + continuous acquire-polls
// from 1024 warps previously hit ONE 128B line per gm.
__device__ ull g_flags[2][16][32];

// ---------------- Kernel A: C = x @ W + bias  (r10-exact, best measured) ---
__global__ __launch_bounds__(256) void gemm_xw_kernel(
    const float* __restrict__ X, const float* __restrict__ W,
    const float* __restrict__ bias, float* __restrict__ C)
{
    __shared__ float As[16][132];
    __shared__ float Bs[16][132];

    const int tid   = threadIdx.x;
    const int tx    = tid & 15;
    const int ty    = tid >> 4;
    const int mBase = blockIdx.y << 7;
    const int nBase = blockIdx.x << 7;

    ull acc[4][8];
#pragma unroll
    for (int p = 0; p < 4; ++p)
#pragma unroll
        for (int n = 0; n < 8; ++n) acc[p][n] = 0ull;

    for (int k0 = 0; k0 < DIN; k0 += 16) {
#pragma unroll
        for (int p = 0; p < 2; ++p) {
            int idx = tid + p * 256;
            int m = idx >> 2, kq = (idx & 3) << 2;
            float4 v = *(const float4*)(X + (size_t)(mBase + m) * DIN + k0 + kq);
            As[kq + 0][m] = v.x;
            As[kq + 1][m] = v.y;
            As[kq + 2][m] = v.z;
            As[kq + 3][m] = v.w;
        }
#pragma unroll
        for (int p = 0; p < 2; ++p) {
            int idx = tid + p * 256;
            int k = idx >> 5, nq = (idx & 31) << 2;
            *(float4*)&Bs[k][nq] = *(const float4*)(W + (size_t)(k0 + k) * DH + nBase + nq);
        }
        __syncthreads();
#pragma unroll
        for (int kk = 0; kk < 16; ++kk) {
            float4 a0 = *(const float4*)&As[kk][ty * 8];
            float4 a1 = *(const float4*)&As[kk][ty * 8 + 4];
            float4 b0 = *(const float4*)&Bs[kk][tx * 8];
            float4 b1 = *(const float4*)&Bs[kk][tx * 8 + 4];
            ull am[4];
            am[0] = f2u(make_float2(a0.x, a0.y));
            am[1] = f2u(make_float2(a0.z, a0.w));
            am[2] = f2u(make_float2(a1.x, a1.y));
            am[3] = f2u(make_float2(a1.z, a1.w));
            ull bn[8];
            bn[0] = pack2(b0.x); bn[1] = pack2(b0.y); bn[2] = pack2(b0.z); bn[3] = pack2(b0.w);
            bn[4] = pack2(b1.x); bn[5] = pack2(b1.y); bn[6] = pack2(b1.z); bn[7] = pack2(b1.w);
#pragma unroll
            for (int p = 0; p < 4; ++p)
#pragma unroll
                for (int n = 0; n < 8; ++n)
                    fma2(acc[p][n], am[p], bn[n]);
        }
        __syncthreads();
    }

    float4 bb0 = *(const float4*)(bias + nBase + tx * 8);
    float4 bb1 = *(const float4*)(bias + nBase + tx * 8 + 4);
    float bbs[8] = {bb0.x, bb0.y, bb0.z, bb0.w, bb1.x, bb1.y, bb1.z, bb1.w};

#pragma unroll
    for (int p = 0; p < 4; ++p) {
        float2 c[8];
#pragma unroll
        for (int n = 0; n < 8; ++n) c[n] = u2f(acc[p][n]);
        int row0 = mBase + ty * 8 + p * 2;
        float* out0 = C + (size_t)row0 * DH + nBase + tx * 8;
        float* out1 = out0 + DH;
        float4 o;
        o.x = c[0].x + bbs[0]; o.y = c[1].x + bbs[1]; o.z = c[2].x + bbs[2]; o.w = c[3].x + bbs[3];
        *(float4*)out0 = o;
        o.x = c[4].x + bbs[4]; o.y = c[5].x + bbs[5]; o.z = c[6].x + bbs[6]; o.w = c[7].x + bbs[7];
        *(float4*)(out0 + 4) = o;
        o.x = c[0].y + bbs[0]; o.y = c[1].y + bbs[1]; o.z = c[2].y + bbs[2]; o.w = c[3].y + bbs[3];
        *(float4*)out1 = o;
        o.x = c[4].y + bbs[4]; o.y = c[5].y + bbs[5]; o.z = c[6].y + bbs[6]; o.w = c[7].y + bbs[7];
        *(float4*)(out1 + 4) = o;
    }
}

// ---------------- Kernel B: persistent recurrence (r10 + padded flags) -----
// 128 blocks: gm = bid>>6 (m-tile 32), gn = bid&63 (j-tile 16). 16 warps.
// Warp w owns k-range [64w,+64), waits on flag[gm][w] (producers 4w..4w+3),
// all-lane poll. h staged per warp via cp.async.cg in TWO k-half groups
// (compute half 0 overlaps landing of half 1). R persistent in smem [j][k].
// f32x2 broadcast micro-tile 4x4. Partials: conflict-free layout
// P[w*512 + 32*(mi*4+ji) + m_lane*4 + j_lane]; reduce reads contiguous.
#define TPB 512
#define HSTRIDE 1028
#define H_OFF 0
#define R_OFF (32 * HSTRIDE)                  // 32896
#define P_OFF (R_OFF + 16 * HSTRIDE)          // 49344
#define SMEM_FLOATS (P_OFF + 16 * 512)        // 57536 floats = 230144 B

__global__ __launch_bounds__(TPB, 1)
void rnn_recur_kernel(const float* __restrict__ h0, const float* __restrict__ R, float* out)
{
    extern __shared__ float S[];

    const int tid    = threadIdx.x;
    const int w      = tid >> 5;
    const int lane   = tid & 31;
    const int m_lane = lane & 7;
    const int j_lane = lane >> 3;
    const int gm     = (int)(blockIdx.x >> 6);
    const int gn     = (int)(blockIdx.x & 63);
    const int mBase  = gm << 5;
    const int jBase  = gn << 4;

    const ull* myflag = &g_flags[gm][w][0];
    ull* prodflag     = &g_flags[gm][gn >> 2][0];

    // snapshot monotonic flag base (all flags equal at kernel entry)
    ull base0 = 0;
    if (lane == 0) base0 = ld_acq(myflag);
    const ull base = __shfl_sync(0xFFFFFFFFu, base0, 0);

    // ---- stage R transposed into smem [j][k] (once) ----
#pragma unroll
    for (int p = 0; p < 8; ++p) {
        int idx = tid + p * TPB;
        int k = idx >> 2, q = idx & 3;
        float4 v = *(const float4*)(R + (size_t)k * DH + jBase + q * 4);
        S[R_OFF + (q * 4 + 0) * HSTRIDE + k] = v.x;
        S[R_OFF + (q * 4 + 1) * HSTRIDE + k] = v.y;
        S[R_OFF + (q * 4 + 2) * HSTRIDE + k] = v.z;
        S[R_OFF + (q * 4 + 3) * HSTRIDE + k] = v.w;
    }
    __syncthreads();

    const float* Hp = S + H_OFF + (size_t)m_lane * HSTRIDE + w * 64;
    const float* Rp = S + R_OFF + (size_t)j_lane * HSTRIDE + w * 64;

    // epilogue decode: tid -> (m, j) matching conflict-free P layout
    const int sub  = tid >> 5;
    const int mi_r = sub >> 2, ji_r = sub & 3;
    const int m_r  = ((tid & 31) >> 2) + 8 * mi_r;
    const int j_r  = (tid & 3) + 4 * ji_r;

    // staging decode: group g covers k in [w*64 + g*32, +32).
    const int klocal = (lane & 7) * 4;
    const int rbase  = lane >> 3;

#pragma unroll 1
    for (int t = 0; t < TSTEPS; ++t) {
        // ---- prefetch this block's preact (own tile; L1-bypass) ----
        const size_t oi = ((size_t)(mBase + m_r) * TSTEPS + t) * DH + jBase + j_r;
        const float pre = __ldcg(out + oi);

        // ---- wait for my chunk's 4 producers to finish step t-1 ----
        if (t > 0) {
            const ull target = base + 4ull * (ull)t;
            while (ld_acq(myflag) < target) { }
        }

        // ---- stage h slice via cp.async in 2 k-half groups ----
        const float* hb;
        size_t rstr;
        if (t == 0) { hb = h0 + (size_t)mBase * DH; rstr = DH; }
        else {
            hb = out + (size_t)(t - 1) * DH + (size_t)mBase * ((size_t)TSTEPS * DH);
            rstr = (size_t)TSTEPS * DH;
        }
#pragma unroll
        for (int g = 0; g < 2; ++g) {
            const int kb = w * 64 + g * 32 + klocal;
#pragma unroll
            for (int p = 0; p < 8; ++p) {
                const int row = rbase + 4 * p;
                cp_async16(s2u(&S[H_OFF + row * HSTRIDE + kb]),
                           hb + (size_t)row * rstr + kb);
            }
            cp_commit();
        }

        ull acc[4][4];
#pragma unroll
        for (int mi = 0; mi < 4; ++mi)
#pragma unroll
            for (int ji = 0; ji < 4; ++ji) acc[mi][ji] = 0ull;

        // ---- compute half 0 while half 1 lands ----
        cp_wait<1>(); __syncwarp();
#pragma unroll
        for (int it = 0; it < 8; ++it) {
            const int off = it * 4;
            float4 h[4], r[4];
#pragma unroll
            for (int mi = 0; mi < 4; ++mi)
                h[mi] = *(const float4*)(Hp + (size_t)(mi * 8) * HSTRIDE + off);
#pragma unroll
            for (int ji = 0; ji < 4; ++ji)
                r[ji] = *(const float4*)(Rp + (size_t)(ji * 4) * HSTRIDE + off);
#pragma unroll
            for (int mi = 0; mi < 4; ++mi) {
                ull hlo = f2u(make_float2(h[mi].x, h[mi].y));
                ull hhi = f2u(make_float2(h[mi].z, h[mi].w));
#pragma unroll
                for (int ji = 0; ji < 4; ++ji) {
                    fma2(acc[mi][ji], hlo, f2u(make_float2(r[ji].x, r[ji].y)));
                    fma2(acc[mi][ji], hhi, f2u(make_float2(r[ji].z, r[ji].w)));
                }
            }
        }

        // ---- compute half 1 ----
        cp_wait<0>(); __syncwarp();
#pragma unroll
        for (int it = 8; it < 16; ++it) {
            const int off = it * 4;
            float4 h[4], r[4];
#pragma unroll
            for (int mi = 0; mi < 4; ++mi)
                h[mi] = *(const float4*)(Hp + (size_t)(mi * 8) * HSTRIDE + off);
#pragma unroll
            for (int ji = 0; ji < 4; ++ji)
                r[ji] = *(const float4*)(Rp + (size_t)(ji * 4) * HSTRIDE + off);
#pragma unroll
            for (int mi = 0; mi < 4; ++mi) {
                ull hlo = f2u(make_float2(h[mi].x, h[mi].y));
                ull hhi = f2u(make_float2(h[mi].z, h[mi].w));
#pragma unroll
                for (int ji = 0; ji < 4; ++ji) {
                    fma2(acc[mi][ji], hlo, f2u(make_float2(r[ji].x, r[ji].y)));
                    fma2(acc[mi][ji], hhi, f2u(make_float2(r[ji].z, r[ji].w)));
                }
            }
        }

        // ---- partials: conflict-free writes (32 lanes -> 32 banks) ----
        {
            float* Pw = S + P_OFF + w * 512;
            const int lbase = m_lane * 4 + j_lane;
#pragma unroll
            for (int mi = 0; mi < 4; ++mi)
#pragma unroll
                for (int ji = 0; ji < 4; ++ji) {
                    float2 c = u2f(acc[mi][ji]);
                    Pw[32 * (mi * 4 + ji) + lbase] = c.x + c.y;
                }
        }
        __syncthreads();   // (a) partials visible

        // ---- reduce 16 partials (contiguous reads) + tanh + store h_t ----
        {
            float s0 = 0.f, s1 = 0.f, s2 = 0.f, s3 = 0.f;
#pragma unroll
            for (int q = 0; q < 4; ++q) {
                s0 += S[P_OFF + (q +  0) * 512 + tid];
                s1 += S[P_OFF + (q +  4) * 512 + tid];
                s2 += S[P_OFF + (q +  8) * 512 + tid];
                s3 += S[P_OFF + (q + 12) * 512 + tid];
            }
            out[oi] = tanhf(pre + (s0 + s1) + (s2 + s3));
        }

        __syncthreads();   // (b) STGs + P reads done (WAR + release ordering)

        // ---- announce: this block finished step t ----
        if (tid == 0) red_rel_add(prodflag, 1ull);
    }
}

// ---------------- launch ----------------
extern "C" void kernel_launch(void* const* d_in, const int* in_sizes, int n_in,
                              void* d_out, int out_size)
{
    const float* x  = (const float*)d_in[0];   // [64,512,512]
    const float* h0 = (const float*)d_in[1];   // [64,1024]
    const float* W  = (const float*)d_in[2];   // [512,1024]
    const float* R  = (const float*)d_in[3];   // [1024,1024]
    const float* b  = (const float*)d_in[4];   // [1,1024]
    float* out = (float*)d_out;                // [64,512,1024]

    const int smem_bytes = SMEM_FLOATS * 4;    // 230144 <= 232448
    cudaFuncSetAttribute(rnn_recur_kernel,
                         cudaFuncAttributeMaxDynamicSharedMemorySize, smem_bytes);

    dim3 gridA(DH / 128, (BATCH * TSTEPS) / 128);  // (8, 256)
    gemm_xw_kernel<<<gridA, 256>>>(x, W, b, out);

    rnn_recur_kernel<<<128, TPB, smem_bytes>>>(h0, R, out);
}